// round 9
// baseline (speedup 1.0000x reference)
#include <cuda_runtime.h>

#define B_ 512
#define N_ 64
#define L_ 64
#define D_ 100
#define NNODES 50000
#define NLOGITS 49999
#define ROWS (B_*N_)   // 32768

// ---------------- scratch (device globals; no allocation allowed) ----------
__device__ float g_fin[ROWS*D_];        // h
__device__ float g_fi [ROWS*D_];
__device__ float g_fo [ROWS*D_];
__device__ float g_x1 [ROWS*3*D_];      // [av(200) | h(100)]
__device__ float g_gates[ROWS*2*D_];    // [r(100) | u(100)]
__device__ float g_x2 [ROWS*3*D_];      // [av(200) | r*h(100)]
__device__ float g_re [ROWS*D_];
__device__ float g_seqh[B_*L_*D_];
__device__ float g_seq [B_*L_*D_];
__device__ float g_lasth[B_*D_];
__device__ float g_last [B_*D_];
__device__ float g_ma   [B_*D_];
__device__ float g_logp [B_];

// ---------------- fast math: FMA-poly exp (avoid MUFU throughput wall) -----
__device__ __forceinline__ float fexp(float x){
    x = fminf(fmaxf(x, -87.0f), 87.0f);
    float n = rintf(x * 1.4426950408889634f);
    float f = fmaf(n, -0.693359375f, x);
    f = fmaf(n, 2.12194440054690583e-4f, f);
    float p = 1.3888889e-3f;
    p = fmaf(p, f, 8.3333333e-3f);
    p = fmaf(p, f, 4.1666667e-2f);
    p = fmaf(p, f, 1.6666667e-1f);
    p = fmaf(p, f, 0.5f);
    p = fmaf(p, f, 1.0f);
    p = fmaf(p, f, 1.0f);
    int e = (int)n;
    float s = __int_as_float((e + 127) << 23);
    return p * s;
}
__device__ __forceinline__ float fsigmoid(float x){
    return __fdividef(1.0f, 1.0f + fexp(-x));
}
__device__ __forceinline__ float ftanh(float x){
    return __fdividef(2.0f, 1.0f + fexp(-2.0f * x)) - 1.0f;
}

// ---------------- generic register-tiled GEMM: C = act(A[M,K] @ W[K,N] + b)
// BLK 64x64, BK=25 (K must be a multiple of 25: 100 or 300 here)
// MODE 0: none; MODE 1: sigmoid; MODE 2: GRU candidate+update epilogue
template<int MODE>
__global__ void gemm64(const float* __restrict__ A, const float* __restrict__ W,
                       const float* __restrict__ bias, float* __restrict__ C,
                       int M, int K, int N)
{
    __shared__ float sA[64][25];
    __shared__ float sW[25][64];
    int m0 = blockIdx.y * 64;
    int n0 = blockIdx.x * 64;
    int tid = threadIdx.x;
    int tx = tid & 15, ty = tid >> 4;
    float acc[4][4] = {};

    for (int k0 = 0; k0 < K; k0 += 25){
        for (int t = tid; t < 64*25; t += 256){
            int r = t / 25, c = t % 25;
            sA[r][c] = (m0 + r < M) ? A[(m0 + r) * K + k0 + c] : 0.0f;
        }
        for (int t = tid; t < 25*64; t += 256){
            int kk = t >> 6, j = t & 63;
            int n = n0 + j;
            sW[kk][j] = (n < N) ? W[(k0 + kk) * N + n] : 0.0f;
        }
        __syncthreads();
        #pragma unroll
        for (int kk = 0; kk < 25; kk++){
            float a0 = sA[ty*4+0][kk];
            float a1 = sA[ty*4+1][kk];
            float a2 = sA[ty*4+2][kk];
            float a3 = sA[ty*4+3][kk];
            float4 w = *(const float4*)&sW[kk][tx*4];
            acc[0][0] = fmaf(a0, w.x, acc[0][0]); acc[0][1] = fmaf(a0, w.y, acc[0][1]);
            acc[0][2] = fmaf(a0, w.z, acc[0][2]); acc[0][3] = fmaf(a0, w.w, acc[0][3]);
            acc[1][0] = fmaf(a1, w.x, acc[1][0]); acc[1][1] = fmaf(a1, w.y, acc[1][1]);
            acc[1][2] = fmaf(a1, w.z, acc[1][2]); acc[1][3] = fmaf(a1, w.w, acc[1][3]);
            acc[2][0] = fmaf(a2, w.x, acc[2][0]); acc[2][1] = fmaf(a2, w.y, acc[2][1]);
            acc[2][2] = fmaf(a2, w.z, acc[2][2]); acc[2][3] = fmaf(a2, w.w, acc[2][3]);
            acc[3][0] = fmaf(a3, w.x, acc[3][0]); acc[3][1] = fmaf(a3, w.y, acc[3][1]);
            acc[3][2] = fmaf(a3, w.z, acc[3][2]); acc[3][3] = fmaf(a3, w.w, acc[3][3]);
        }
        __syncthreads();
    }

    #pragma unroll
    for (int q = 0; q < 4; q++){
        int row = m0 + ty*4 + q;
        if (row >= M) continue;
        #pragma unroll
        for (int p = 0; p < 4; p++){
            int col = n0 + tx*4 + p;
            if (col >= N) continue;
            float v = acc[q][p];
            if (bias) v += bias[col];
            if (MODE == 1) v = fsigmoid(v);
            if (MODE == 2){
                float c = ftanh(v);
                float u = g_gates[row*200 + 100 + col];
                float h = g_fin[row*100 + col];
                v = u*h + (1.0f - u)*c;
            }
            C[(long long)row * N + col] = v;
        }
    }
}

// ---------------- logits: C[m,n] = dot(A[m,:], E[n,:])  (NT layout) --------
__global__ void gemm_nt_logits(const float* __restrict__ A, const float* __restrict__ E,
                               float* __restrict__ C, int M, long long NC)
{
    __shared__ float sA[64][25];
    __shared__ float sE[64][25];
    int m0 = blockIdx.y * 64;
    long long n0 = (long long)blockIdx.x * 64;
    int tid = threadIdx.x;
    int tx = tid & 15, ty = tid >> 4;
    float acc[4][4] = {};

    for (int k0 = 0; k0 < 100; k0 += 25){
        for (int t = tid; t < 64*25; t += 256){
            int r = t / 25, c = t % 25;
            sA[r][c] = (m0 + r < M) ? A[(m0 + r) * 100 + k0 + c] : 0.0f;
        }
        for (int t = tid; t < 64*25; t += 256){
            int r = t / 25, c = t % 25;
            long long n = n0 + r;
            sE[r][c] = (n < NC) ? E[n * 100 + k0 + c] : 0.0f;
        }
        __syncthreads();
        #pragma unroll
        for (int kk = 0; kk < 25; kk++){
            float a0 = sA[ty*4+0][kk];
            float a1 = sA[ty*4+1][kk];
            float a2 = sA[ty*4+2][kk];
            float a3 = sA[ty*4+3][kk];
            float e0 = sE[tx*4+0][kk];
            float e1 = sE[tx*4+1][kk];
            float e2 = sE[tx*4+2][kk];
            float e3 = sE[tx*4+3][kk];
            acc[0][0] = fmaf(a0, e0, acc[0][0]); acc[0][1] = fmaf(a0, e1, acc[0][1]);
            acc[0][2] = fmaf(a0, e2, acc[0][2]); acc[0][3] = fmaf(a0, e3, acc[0][3]);
            acc[1][0] = fmaf(a1, e0, acc[1][0]); acc[1][1] = fmaf(a1, e1, acc[1][1]);
            acc[1][2] = fmaf(a1, e2, acc[1][2]); acc[1][3] = fmaf(a1, e3, acc[1][3]);
            acc[2][0] = fmaf(a2, e0, acc[2][0]); acc[2][1] = fmaf(a2, e1, acc[2][1]);
            acc[2][2] = fmaf(a2, e2, acc[2][2]); acc[2][3] = fmaf(a2, e3, acc[2][3]);
            acc[3][0] = fmaf(a3, e0, acc[3][0]); acc[3][1] = fmaf(a3, e1, acc[3][1]);
            acc[3][2] = fmaf(a3, e2, acc[3][2]); acc[3][3] = fmaf(a3, e3, acc[3][3]);
        }
        __syncthreads();
    }
    #pragma unroll
    for (int q = 0; q < 4; q++){
        int row = m0 + ty*4 + q;
        if (row >= M) continue;
        #pragma unroll
        for (int p = 0; p < 4; p++){
            long long col = n0 + tx*4 + p;
            if (col >= NC) continue;
            C[(long long)row * NC + col] = acc[q][p];
        }
    }
}

// ---------------- small kernels --------------------------------------------
__global__ void k_gather(const float* __restrict__ emb, const int* __restrict__ item){
    int t = blockIdx.x * 256 + threadIdx.x;
    if (t >= ROWS * D_) return;
    int idx = t / D_, d = t % D_;
    float v = emb[(long long)item[idx] * D_ + d];
    g_fin[t] = v;
    g_x1[idx * 300 + 200 + d] = v;   // h-part of concat for gates GEMM
}

// av = [adj_in @ fi | adj_out @ fo] -> x1[:, 0:200]
__global__ void k_av(const float* __restrict__ adj_in, const float* __restrict__ adj_out){
    int b = blockIdx.x;
    __shared__ float sAi[64*64];
    __shared__ float sAo[64*64];
    for (int t = threadIdx.x; t < 4096; t += 256){
        sAi[t] = adj_in [b*4096 + t];
        sAo[t] = adj_out[b*4096 + t];
    }
    __syncthreads();
    const float* fi = g_fi + b*64*100;
    const float* fo = g_fo + b*64*100;
    float* x1 = g_x1 + b*64*300;
    for (int t = threadIdx.x; t < 100*16; t += 256){
        int e = t % 100, iq = t / 100;
        int i0 = iq * 4;
        float aI[4] = {0,0,0,0}, aO[4] = {0,0,0,0};
        for (int j = 0; j < 64; j++){
            float vI = __ldg(&fi[j*100 + e]);
            float vO = __ldg(&fo[j*100 + e]);
            #pragma unroll
            for (int q = 0; q < 4; q++){
                aI[q] = fmaf(sAi[(i0+q)*64 + j], vI, aI[q]);
                aO[q] = fmaf(sAo[(i0+q)*64 + j], vO, aO[q]);
            }
        }
        #pragma unroll
        for (int q = 0; q < 4; q++){
            x1[(i0+q)*300 + e]       = aI[q];
            x1[(i0+q)*300 + 100 + e] = aO[q];
        }
    }
}

// x2 = [av | r*h]
__global__ void k_x2(){
    int t = blockIdx.x * 256 + threadIdx.x;
    if (t >= ROWS * 300) return;
    int row = t / 300, c = t % 300;
    float v;
    if (c < 200) v = g_x1[t];
    else {
        int d = c - 200;
        v = g_gates[row*200 + d] * g_fin[row*100 + d];
    }
    g_x2[t] = v;
}

// per-batch: rm, last_id, gather seq_h and last_h
__global__ void k_nasr(const int* __restrict__ alias, const float* __restrict__ mask){
    int b = blockIdx.x;
    __shared__ int s_alias[64];
    __shared__ int s_last;
    if (threadIdx.x < 64) s_alias[threadIdx.x] = alias[b*64 + threadIdx.x];
    __syncthreads();
    if (threadIdx.x == 0){
        float s = 0.0f;
        for (int l = 0; l < 64; l++) s += mask[b*64 + l];
        int rm = (int)(s + 0.5f);
        if (rm < 1) rm = 1;
        s_last = s_alias[rm - 1];
    }
    __syncthreads();
    for (int t = threadIdx.x; t < 64*100; t += 256){
        int l = t / 100, d = t % 100;
        g_seqh[(b*64 + l)*100 + d] = g_re[(b*64 + s_alias[l])*100 + d];
    }
    for (int d = threadIdx.x; d < 100; d += 256)
        g_lasth[b*100 + d] = g_re[(b*64 + s_last)*100 + d];
}

// attention: coef + weighted sum -> ma
__global__ void k_attn(const float* __restrict__ mask, const float* __restrict__ nasr_v,
                       const float* __restrict__ nasr_b){
    int b = blockIdx.x;
    int tid = threadIdx.x;               // 128 threads
    __shared__ float s_last[100], s_v[100], s_nb[100], s_coef[64];
    if (tid < 100){
        s_last[tid] = g_last[b*100 + tid];
        s_v[tid]    = nasr_v[tid];
        s_nb[tid]   = nasr_b[tid];
    }
    __syncthreads();
    int w = tid >> 5, lane = tid & 31;
    for (int l = w; l < 64; l += 4){
        float part = 0.0f;
        for (int d = lane; d < 100; d += 32){
            float x = s_last[d] + g_seq[(b*64 + l)*100 + d] + s_nb[d];
            part = fmaf(fsigmoid(x), s_v[d], part);
        }
        #pragma unroll
        for (int o = 16; o > 0; o >>= 1) part += __shfl_down_sync(0xffffffffu, part, o);
        if (lane == 0) s_coef[l] = part * mask[b*64 + l];
    }
    __syncthreads();
    for (int d = tid; d < 100; d += 128){
        float acc = 0.0f;
        for (int l = 0; l < 64; l++)
            acc = fmaf(s_coef[l], g_seqh[(b*64 + l)*100 + d], acc);
        g_ma[b*100 + d] = acc;
    }
}

// per-row online max/sumexp over logits, then logp[label]
__global__ void k_rowstat(const float* __restrict__ logits, const int* __restrict__ tar){
    int b = blockIdx.x;
    const float* row = logits + (long long)b * NLOGITS;
    int tid = threadIdx.x;
    float m = -1e30f, s = 0.0f;
    for (int j = tid; j < NLOGITS; j += 256){
        float x = row[j];
        if (x > m){ s = fmaf(s, fexp(m - x), 1.0f); m = x; }
        else       s += fexp(x - m);
    }
    __shared__ float sm[256], ss[256];
    sm[tid] = m; ss[tid] = s;
    __syncthreads();
    for (int o = 128; o > 0; o >>= 1){
        if (tid < o){
            float m2 = sm[tid+o], s2 = ss[tid+o];
            float M = fmaxf(sm[tid], m2);
            ss[tid] = ss[tid]*fexp(sm[tid]-M) + s2*fexp(m2-M);
            sm[tid] = M;
        }
        __syncthreads();
    }
    if (tid == 0){
        int lab = tar[b] - 1;
        g_logp[b] = row[lab] - sm[0] - logf(ss[0]);
    }
}

__global__ void k_loss(float* __restrict__ out, int off){
    __shared__ float sh[512];
    int tid = threadIdx.x;
    sh[tid] = g_logp[tid];
    __syncthreads();
    for (int o = 256; o > 0; o >>= 1){
        if (tid < o) sh[tid] += sh[tid+o];
        __syncthreads();
    }
    if (tid == 0){
        float loss = -sh[0] / (float)B_;
        for (int i = 0; i < off; i++) out[i] = loss;
    }
}

// ---------------- host ------------------------------------------------------
static float* symf(const void* s){ void* p = nullptr; cudaGetSymbolAddress(&p, s); return (float*)p; }

extern "C" void kernel_launch(void* const* d_in, const int* in_sizes, int n_in,
                              void* d_out, int out_size)
{
    const float* adj_in   = (const float*)d_in[0];
    const float* adj_out  = (const float*)d_in[1];
    const int*   item     = (const int*)  d_in[2];
    const int*   alias    = (const int*)  d_in[3];
    const float* mask     = (const float*)d_in[4];
    const int*   tar      = (const int*)  d_in[5];
    const float* emb      = (const float*)d_in[6];
    const float* W_in     = (const float*)d_in[7];
    const float* b_in     = (const float*)d_in[8];
    const float* W_out    = (const float*)d_in[9];
    const float* b_out    = (const float*)d_in[10];
    const float* gate_k   = (const float*)d_in[11];
    const float* gate_b   = (const float*)d_in[12];
    const float* cand_k   = (const float*)d_in[13];
    const float* cand_b   = (const float*)d_in[14];
    const float* nasr_w1  = (const float*)d_in[15];
    const float* nasr_w2  = (const float*)d_in[16];
    const float* nasr_v   = (const float*)d_in[17];
    const float* nasr_b   = (const float*)d_in[18];

    float* out = (float*)d_out;
    long long nlog = (long long)B_ * NLOGITS;
    int off = out_size - (int)nlog;
    if (off < 0) off = 0;
    float* out_logits = out + off;

    float* p_fin   = symf(g_fin);
    float* p_fi    = symf(g_fi);
    float* p_fo    = symf(g_fo);
    float* p_x1    = symf(g_x1);
    float* p_gates = symf(g_gates);
    float* p_x2    = symf(g_x2);
    float* p_re    = symf(g_re);
    float* p_seqh  = symf(g_seqh);
    float* p_seq   = symf(g_seq);
    float* p_lasth = symf(g_lasth);
    float* p_last  = symf(g_last);
    float* p_ma    = symf(g_ma);

    // 1. gather embeddings (also fills h-part of x1)
    k_gather<<<(ROWS*D_ + 255)/256, 256>>>(emb, item);
    // 2. fi = fin@W_in + b_in ; fo = fin@W_out + b_out
    gemm64<0><<<dim3(2, ROWS/64), 256>>>(p_fin, W_in,  b_in,  p_fi, ROWS, 100, 100);
    gemm64<0><<<dim3(2, ROWS/64), 256>>>(p_fin, W_out, b_out, p_fo, ROWS, 100, 100);
    // 3. av = [adj_in@fi | adj_out@fo] -> x1[:,0:200]
    k_av<<<B_, 256>>>(adj_in, adj_out);
    // 4. gates = sigmoid(x1 @ gate_kernel + gate_bias)
    gemm64<1><<<dim3(4, ROWS/64), 256>>>(p_x1, gate_k, gate_b, p_gates, ROWS, 300, 200);
    // 5. x2 = [av | r*h]
    k_x2<<<(ROWS*300 + 255)/256, 256>>>();
    // 6. c = tanh(x2 @ cand_kernel + cand_bias); re = u*h + (1-u)*c
    gemm64<2><<<dim3(2, ROWS/64), 256>>>(p_x2, cand_k, cand_b, p_re, ROWS, 300, 100);
    // 7. nasr gathers
    k_nasr<<<B_, 256>>>(alias, mask);
    // 8. seq = seqh @ nasr_w2 ; last = lasth @ nasr_w1
    gemm64<0><<<dim3(2, ROWS/64), 256>>>(p_seqh, nasr_w2, nullptr, p_seq, ROWS, 100, 100);
    gemm64<0><<<dim3(2, B_/64), 256>>>(p_lasth, nasr_w1, nullptr, p_last, B_, 100, 100);
    // 9. attention -> ma
    k_attn<<<B_, 128>>>(mask, nasr_v, nasr_b);
    // 10. logits = ma @ emb[1:].T
    gemm_nt_logits<<<dim3((NLOGITS + 63)/64, B_/64), 256>>>(p_ma, emb + D_, out_logits, B_, (long long)NLOGITS);
    // 11. per-row log-softmax stats + loss
    k_rowstat<<<B_, 256>>>(out_logits, tar);
    k_loss<<<1, 512>>>(out, off);
}

// round 14
// speedup vs baseline: 1.9457x; 1.9457x over previous
#include <cuda_runtime.h>
#include <cstdint>

#define B_ 512
#define N_ 64
#define L_ 64
#define D_ 100
#define NNODES 50000
#define NLOGITS 49999
#define ROWS (B_*N_)   // 32768

// ---------------- scratch (device globals; no allocation allowed) ----------
__device__ float g_fin[ROWS*D_];        // h
__device__ float g_fi [ROWS*D_];
__device__ float g_fo [ROWS*D_];
__device__ float g_x1 [ROWS*3*D_];      // [av(200) | h(100)]
__device__ float g_gates[ROWS*2*D_];    // [r(100) | u(100)]
__device__ float g_x2 [ROWS*3*D_];      // [av(200) | r*h(100)]
__device__ float g_re [ROWS*D_];
__device__ float g_seqh[B_*L_*D_];
__device__ float g_seq [B_*L_*D_];
__device__ float g_lasth[B_*D_];
__device__ float g_last [B_*D_];
__device__ float g_ma   [B_*D_];
__device__ float g_logp [B_];

// ---------------- fast math: FMA-poly exp (avoid MUFU throughput wall) -----
__device__ __forceinline__ float fexp(float x){
    x = fminf(fmaxf(x, -87.0f), 87.0f);
    float n = rintf(x * 1.4426950408889634f);
    float f = fmaf(n, -0.693359375f, x);
    f = fmaf(n, 2.12194440054690583e-4f, f);
    float p = 1.3888889e-3f;
    p = fmaf(p, f, 8.3333333e-3f);
    p = fmaf(p, f, 4.1666667e-2f);
    p = fmaf(p, f, 1.6666667e-1f);
    p = fmaf(p, f, 0.5f);
    p = fmaf(p, f, 1.0f);
    p = fmaf(p, f, 1.0f);
    int e = (int)n;
    float s = __int_as_float((e + 127) << 23);
    return p * s;
}
__device__ __forceinline__ float fsigmoid(float x){
    return __fdividef(1.0f, 1.0f + fexp(-x));
}
__device__ __forceinline__ float ftanh(float x){
    return __fdividef(2.0f, 1.0f + fexp(-2.0f * x)) - 1.0f;
}

// ---------------- TF32 mma helpers ----------------------------------------
__device__ __forceinline__ void mma8(float* d,
                                     uint32_t a0, uint32_t a1, uint32_t a2, uint32_t a3,
                                     uint32_t b0, uint32_t b1){
    asm volatile(
        "mma.sync.aligned.m16n8k8.row.col.f32.tf32.tf32.f32 "
        "{%0,%1,%2,%3}, {%4,%5,%6,%7}, {%8,%9}, {%0,%1,%2,%3};\n"
        : "+f"(d[0]), "+f"(d[1]), "+f"(d[2]), "+f"(d[3])
        : "r"(a0), "r"(a1), "r"(a2), "r"(a3), "r"(b0), "r"(b1));
}
// split fp32 into tf32-exact hi part and exact residual lo (hi = top 19 bits)
__device__ __forceinline__ void split_tf32(float f, uint32_t& hi, uint32_t& lo){
    uint32_t b = __float_as_uint(f);
    hi = b & 0xffffe000u;
    lo = __float_as_uint(f - __uint_as_float(hi));
}

// ---------------- TF32x3 tensor-core GEMM: C = act(A[M,K] @ W[K,N] + b) ----
// BM=128, BN=64, BK=32. 8 warps = 4 (m) x 2 (n); warp tile 32x32.
// sA row stride 36 (==4 mod 32)  -> A-frag LDS conflict-free (bank = 4g+tg)
// sB row stride 72 (==8 mod 32, >=64) -> B-frag LDS conflict-free (bank = 8tg+g)
// MODE 0: optional bias; MODE 1: sigmoid; MODE 2: GRU candidate+update
template<int MODE>
__global__ void __launch_bounds__(256, 2)
gemm_tc(const float* __restrict__ A, const float* __restrict__ W,
        const float* __restrict__ bias, float* __restrict__ C,
        int M, int K, int N)
{
    __shared__ float sA[128*36];
    __shared__ float sB[32*72];
    int m0 = blockIdx.y * 128;
    int n0 = blockIdx.x * 64;
    int tid = threadIdx.x, lane = tid & 31, wid = tid >> 5;
    int wm = wid >> 1, wn = wid & 1;
    int g = lane >> 2, tg = lane & 3;

    float acc[2][4][4] = {};

    int ksteps = (K + 31) / 32;
    for (int kt = 0; kt < ksteps; kt++){
        int k0 = kt * 32;
        // A tile: 128x32 -> 1024 float4
        #pragma unroll
        for (int i = tid; i < 1024; i += 256){
            int r = i >> 3, c4 = (i & 7) * 4;
            float4 v = make_float4(0.f,0.f,0.f,0.f);
            int row = m0 + r, k = k0 + c4;
            if (row < M && k < K)           // K % 4 == 0 at all call sites
                v = *(const float4*)&A[(long long)row * K + k];
            *(float4*)&sA[r*36 + c4] = v;
        }
        // B tile: 32x64 -> 512 float4
        #pragma unroll
        for (int i = tid; i < 512; i += 256){
            int kk = i >> 4, c4 = (i & 15) * 4;
            float4 v = make_float4(0.f,0.f,0.f,0.f);
            int k = k0 + kk, n = n0 + c4;
            if (k < K && n < N)             // N % 4 == 0 at all call sites
                v = *(const float4*)&W[(long long)k * N + n];
            *(float4*)&sB[kk*72 + c4] = v;
        }
        __syncthreads();

        #pragma unroll
        for (int k8 = 0; k8 < 32; k8 += 8){
            uint32_t ah[2][4], al[2][4];
            #pragma unroll
            for (int t = 0; t < 2; t++){
                int rb = wm*32 + t*16;
                float f0 = sA[(rb+g  )*36 + k8+tg  ];
                float f1 = sA[(rb+g+8)*36 + k8+tg  ];
                float f2 = sA[(rb+g  )*36 + k8+tg+4];
                float f3 = sA[(rb+g+8)*36 + k8+tg+4];
                split_tf32(f0, ah[t][0], al[t][0]);
                split_tf32(f1, ah[t][1], al[t][1]);
                split_tf32(f2, ah[t][2], al[t][2]);
                split_tf32(f3, ah[t][3], al[t][3]);
            }
            #pragma unroll
            for (int u = 0; u < 4; u++){
                float b0f = sB[(k8+tg  )*72 + wn*32 + u*8 + g];
                float b1f = sB[(k8+tg+4)*72 + wn*32 + u*8 + g];
                uint32_t bh0, bl0, bh1, bl1;
                split_tf32(b0f, bh0, bl0);
                split_tf32(b1f, bh1, bl1);
                #pragma unroll
                for (int t = 0; t < 2; t++){
                    mma8(acc[t][u], ah[t][0],ah[t][1],ah[t][2],ah[t][3], bl0, bl1);
                    mma8(acc[t][u], al[t][0],al[t][1],al[t][2],al[t][3], bh0, bh1);
                    mma8(acc[t][u], ah[t][0],ah[t][1],ah[t][2],ah[t][3], bh0, bh1);
                }
            }
        }
        __syncthreads();
    }

    #pragma unroll
    for (int t = 0; t < 2; t++){
        #pragma unroll
        for (int u = 0; u < 4; u++){
            #pragma unroll
            for (int i = 0; i < 4; i++){
                int row = m0 + wm*32 + t*16 + g + ((i >= 2) ? 8 : 0);
                int col = n0 + wn*32 + u*8 + tg*2 + (i & 1);
                if (row >= M || col >= N) continue;
                float v = acc[t][u][i];
                if (bias) v += bias[col];
                if (MODE == 1) v = fsigmoid(v);
                if (MODE == 2){
                    float c = ftanh(v);
                    float uu = g_gates[row*200 + 100 + col];
                    float h  = g_fin[row*100 + col];
                    v = uu*h + (1.0f - uu)*c;
                }
                C[(long long)row * N + col] = v;
            }
        }
    }
}

// ---------------- logits (NT): C[m,n] = dot(A[m,:], E[n,:]), TF32x3 -------
__global__ void __launch_bounds__(256, 2)
gemm_nt_tc(const float* __restrict__ A, const float* __restrict__ E,
           float* __restrict__ C, int M, long long NC)
{
    __shared__ float sA[128*36];
    __shared__ float sE[64*36];
    int m0 = blockIdx.y * 128;
    long long n0 = (long long)blockIdx.x * 64;
    int tid = threadIdx.x, lane = tid & 31, wid = tid >> 5;
    int wm = wid >> 1, wn = wid & 1;
    int g = lane >> 2, tg = lane & 3;

    float acc[2][4][4] = {};

    for (int kt = 0; kt < 4; kt++){       // K = 100 padded to 128
        int k0 = kt * 32;
        #pragma unroll
        for (int i = tid; i < 1024; i += 256){
            int r = i >> 3, c4 = (i & 7) * 4;
            float4 v = make_float4(0.f,0.f,0.f,0.f);
            int row = m0 + r, k = k0 + c4;
            if (row < M && k < 100)
                v = *(const float4*)&A[(long long)row * 100 + k];
            *(float4*)&sA[r*36 + c4] = v;
        }
        #pragma unroll
        for (int i = tid; i < 512; i += 256){
            int r = i >> 3, c4 = (i & 7) * 4;
            float4 v = make_float4(0.f,0.f,0.f,0.f);
            long long n = n0 + r;
            int k = k0 + c4;
            if (n < NC && k < 100)
                v = *(const float4*)&E[n * 100 + k];
            *(float4*)&sE[r*36 + c4] = v;
        }
        __syncthreads();

        #pragma unroll
        for (int k8 = 0; k8 < 32; k8 += 8){
            uint32_t ah[2][4], al[2][4];
            #pragma unroll
            for (int t = 0; t < 2; t++){
                int rb = wm*32 + t*16;
                float f0 = sA[(rb+g  )*36 + k8+tg  ];
                float f1 = sA[(rb+g+8)*36 + k8+tg  ];
                float f2 = sA[(rb+g  )*36 + k8+tg+4];
                float f3 = sA[(rb+g+8)*36 + k8+tg+4];
                split_tf32(f0, ah[t][0], al[t][0]);
                split_tf32(f1, ah[t][1], al[t][1]);
                split_tf32(f2, ah[t][2], al[t][2]);
                split_tf32(f3, ah[t][3], al[t][3]);
            }
            #pragma unroll
            for (int u = 0; u < 4; u++){
                int nl = wn*32 + u*8 + g;
                float b0f = sE[nl*36 + k8+tg  ];
                float b1f = sE[nl*36 + k8+tg+4];
                uint32_t bh0, bl0, bh1, bl1;
                split_tf32(b0f, bh0, bl0);
                split_tf32(b1f, bh1, bl1);
                #pragma unroll
                for (int t = 0; t < 2; t++){
                    mma8(acc[t][u], ah[t][0],ah[t][1],ah[t][2],ah[t][3], bl0, bl1);
                    mma8(acc[t][u], al[t][0],al[t][1],al[t][2],al[t][3], bh0, bh1);
                    mma8(acc[t][u], ah[t][0],ah[t][1],ah[t][2],ah[t][3], bh0, bh1);
                }
            }
        }
        __syncthreads();
    }

    #pragma unroll
    for (int t = 0; t < 2; t++){
        #pragma unroll
        for (int u = 0; u < 4; u++){
            #pragma unroll
            for (int i = 0; i < 4; i++){
                int row = m0 + wm*32 + t*16 + g + ((i >= 2) ? 8 : 0);
                long long col = n0 + wn*32 + u*8 + tg*2 + (i & 1);
                if (row >= M || col >= NC) continue;
                C[(long long)row * NC + col] = acc[t][u][i];
            }
        }
    }
}

// ---------------- av via mma: x1[:, OFF..OFF+100) = adj[b] @ F[b] ----------
// per block: one batch. A = adj (64x64), B = F tile (64 k x 100 n, k-major).
// 4 warps, each owns 16 rows x 104 cols (13 n-tiles).
// sAdj stride 68 (==4 mod 32); sF stride 104 (==8 mod 32): conflict-free frags.
template<int OFF>
__global__ void __launch_bounds__(128)
k_av_tc(const float* __restrict__ adj, const float* __restrict__ F)
{
    __shared__ float sAdj[64*68];
    __shared__ float sF[64*104];
    int b = blockIdx.x;
    int tid = threadIdx.x, lane = tid & 31, wid = tid >> 5;
    int g = lane >> 2, tg = lane & 3;

    #pragma unroll
    for (int i = tid; i < 1024; i += 128){          // adj: 64x64
        int r = i >> 4, c4 = (i & 15) * 4;
        *(float4*)&sAdj[r*68 + c4] = *(const float4*)&adj[b*4096 + r*64 + c4];
    }
    #pragma unroll
    for (int i = tid; i < 1600; i += 128){          // F: 64x100
        int r = i / 25, c4 = (i % 25) * 4;
        *(float4*)&sF[r*104 + c4] = *(const float4*)&F[(b*64 + r)*100 + c4];
    }
    for (int r = tid; r < 64; r += 128){            // zero pad cols 100..103
        sF[r*104+100] = 0.f; sF[r*104+101] = 0.f;
        sF[r*104+102] = 0.f; sF[r*104+103] = 0.f;
    }
    __syncthreads();

    float acc[13][4] = {};
    int rb = wid * 16;
    #pragma unroll
    for (int k8 = 0; k8 < 64; k8 += 8){
        float f0 = sAdj[(rb+g  )*68 + k8+tg  ];
        float f1 = sAdj[(rb+g+8)*68 + k8+tg  ];
        float f2 = sAdj[(rb+g  )*68 + k8+tg+4];
        float f3 = sAdj[(rb+g+8)*68 + k8+tg+4];
        uint32_t ah0,al0,ah1,al1,ah2,al2,ah3,al3;
        split_tf32(f0, ah0, al0); split_tf32(f1, ah1, al1);
        split_tf32(f2, ah2, al2); split_tf32(f3, ah3, al3);
        #pragma unroll
        for (int u = 0; u < 13; u++){
            float b0f = sF[(k8+tg  )*104 + u*8 + g];
            float b1f = sF[(k8+tg+4)*104 + u*8 + g];
            uint32_t bh0, bl0, bh1, bl1;
            split_tf32(b0f, bh0, bl0);
            split_tf32(b1f, bh1, bl1);
            mma8(acc[u], ah0,ah1,ah2,ah3, bl0, bl1);
            mma8(acc[u], al0,al1,al2,al3, bh0, bh1);
            mma8(acc[u], ah0,ah1,ah2,ah3, bh0, bh1);
        }
    }

    float* x1 = g_x1 + b*64*300;
    #pragma unroll
    for (int u = 0; u < 13; u++){
        #pragma unroll
        for (int i = 0; i < 4; i++){
            int row = rb + g + ((i >= 2) ? 8 : 0);
            int col = u*8 + tg*2 + (i & 1);
            if (col < 100)
                x1[row*300 + OFF + col] = acc[u][i];
        }
    }
}

// ---------------- small kernels --------------------------------------------
__global__ void k_gather(const float* __restrict__ emb, const int* __restrict__ item){
    int t = blockIdx.x * 256 + threadIdx.x;
    if (t >= ROWS * D_) return;
    int idx = t / D_, d = t % D_;
    float v = emb[(long long)item[idx] * D_ + d];
    g_fin[t] = v;
    g_x1[idx * 300 + 200 + d] = v;   // h-part of concat for gates GEMM
}

// x2 = [av | r*h]
__global__ void k_x2(){
    int t = blockIdx.x * 256 + threadIdx.x;
    if (t >= ROWS * 300) return;
    int row = t / 300, c = t % 300;
    float v;
    if (c < 200) v = g_x1[t];
    else {
        int d = c - 200;
        v = g_gates[row*200 + d] * g_fin[row*100 + d];
    }
    g_x2[t] = v;
}

// per-batch: rm, last_id, gather seq_h and last_h
__global__ void k_nasr(const int* __restrict__ alias, const float* __restrict__ mask){
    int b = blockIdx.x;
    __shared__ int s_alias[64];
    __shared__ int s_last;
    if (threadIdx.x < 64) s_alias[threadIdx.x] = alias[b*64 + threadIdx.x];
    __syncthreads();
    if (threadIdx.x == 0){
        float s = 0.0f;
        for (int l = 0; l < 64; l++) s += mask[b*64 + l];
        int rm = (int)(s + 0.5f);
        if (rm < 1) rm = 1;
        s_last = s_alias[rm - 1];
    }
    __syncthreads();
    for (int t = threadIdx.x; t < 64*100; t += 256){
        int l = t / 100, d = t % 100;
        g_seqh[(b*64 + l)*100 + d] = g_re[(b*64 + s_alias[l])*100 + d];
    }
    for (int d = threadIdx.x; d < 100; d += 256)
        g_lasth[b*100 + d] = g_re[(b*64 + s_last)*100 + d];
}

// attention: coef + weighted sum -> ma
__global__ void k_attn(const float* __restrict__ mask, const float* __restrict__ nasr_v,
                       const float* __restrict__ nasr_b){
    int b = blockIdx.x;
    int tid = threadIdx.x;               // 128 threads
    __shared__ float s_last[100], s_v[100], s_nb[100], s_coef[64];
    if (tid < 100){
        s_last[tid] = g_last[b*100 + tid];
        s_v[tid]    = nasr_v[tid];
        s_nb[tid]   = nasr_b[tid];
    }
    __syncthreads();
    int w = tid >> 5, lane = tid & 31;
    for (int l = w; l < 64; l += 4){
        float part = 0.0f;
        for (int d = lane; d < 100; d += 32){
            float x = s_last[d] + g_seq[(b*64 + l)*100 + d] + s_nb[d];
            part = fmaf(fsigmoid(x), s_v[d], part);
        }
        #pragma unroll
        for (int o = 16; o > 0; o >>= 1) part += __shfl_down_sync(0xffffffffu, part, o);
        if (lane == 0) s_coef[l] = part * mask[b*64 + l];
    }
    __syncthreads();
    for (int d = tid; d < 100; d += 128){
        float acc = 0.0f;
        for (int l = 0; l < 64; l++)
            acc = fmaf(s_coef[l], g_seqh[(b*64 + l)*100 + d], acc);
        g_ma[b*100 + d] = acc;
    }
}

// per-row online max/sumexp over logits, then logp[label]
__global__ void k_rowstat(const float* __restrict__ logits, const int* __restrict__ tar){
    int b = blockIdx.x;
    const float* row = logits + (long long)b * NLOGITS;
    int tid = threadIdx.x;
    float m = -1e30f, s = 0.0f;
    for (int j = tid; j < NLOGITS; j += 256){
        float x = row[j];
        if (x > m){ s = fmaf(s, fexp(m - x), 1.0f); m = x; }
        else       s += fexp(x - m);
    }
    __shared__ float sm[256], ss[256];
    sm[tid] = m; ss[tid] = s;
    __syncthreads();
    for (int o = 128; o > 0; o >>= 1){
        if (tid < o){
            float m2 = sm[tid+o], s2 = ss[tid+o];
            float M = fmaxf(sm[tid], m2);
            ss[tid] = ss[tid]*fexp(sm[tid]-M) + s2*fexp(m2-M);
            sm[tid] = M;
        }
        __syncthreads();
    }
    if (tid == 0){
        int lab = tar[b] - 1;
        g_logp[b] = row[lab] - sm[0] - logf(ss[0]);
    }
}

__global__ void k_loss(float* __restrict__ out, int off){
    __shared__ float sh[512];
    int tid = threadIdx.x;
    sh[tid] = g_logp[tid];
    __syncthreads();
    for (int o = 256; o > 0; o >>= 1){
        if (tid < o) sh[tid] += sh[tid+o];
        __syncthreads();
    }
    if (tid == 0){
        float loss = -sh[0] / (float)B_;
        for (int i = 0; i < off; i++) out[i] = loss;
    }
}

// ---------------- host ------------------------------------------------------
static float* symf(const void* s){ void* p = nullptr; cudaGetSymbolAddress(&p, s); return (float*)p; }

extern "C" void kernel_launch(void* const* d_in, const int* in_sizes, int n_in,
                              void* d_out, int out_size)
{
    const float* adj_in   = (const float*)d_in[0];
    const float* adj_out  = (const float*)d_in[1];
    const int*   item     = (const int*)  d_in[2];
    const int*   alias    = (const int*)  d_in[3];
    const float* mask     = (const float*)d_in[4];
    const int*   tar      = (const int*)  d_in[5];
    const float* emb      = (const float*)d_in[6];
    const float* W_in     = (const float*)d_in[7];
    const float* b_in     = (const float*)d_in[8];
    const float* W_out    = (const float*)d_in[9];
    const float* b_out    = (const float*)d_in[10];
    const float* gate_k   = (const float*)d_in[11];
    const float* gate_b   = (const float*)d_in[12];
    const float* cand_k   = (const float*)d_in[13];
    const float* cand_b   = (const float*)d_in[14];
    const float* nasr_w1  = (const float*)d_in[15];
    const float* nasr_w2  = (const float*)d_in[16];
    const float* nasr_v   = (const float*)d_in[17];
    const float* nasr_b   = (const float*)d_in[18];

    float* out = (float*)d_out;
    long long nlog = (long long)B_ * NLOGITS;
    int off = out_size - (int)nlog;
    if (off < 0) off = 0;
    float* out_logits = out + off;

    float* p_fin   = symf(g_fin);
    float* p_fi    = symf(g_fi);
    float* p_fo    = symf(g_fo);
    float* p_x1    = symf(g_x1);
    float* p_gates = symf(g_gates);
    float* p_x2    = symf(g_x2);
    float* p_re    = symf(g_re);
    float* p_seqh  = symf(g_seqh);
    float* p_seq   = symf(g_seq);
    float* p_lasth = symf(g_lasth);
    float* p_last  = symf(g_last);
    float* p_ma    = symf(g_ma);

    // 1. gather embeddings (also fills h-part of x1)
    k_gather<<<(ROWS*D_ + 255)/256, 256>>>(emb, item);
    // 2. fi = fin@W_in + b_in ; fo = fin@W_out + b_out   (TF32x3 mma)
    gemm_tc<0><<<dim3(2, ROWS/128), 256>>>(p_fin, W_in,  b_in,  p_fi, ROWS, 100, 100);
    gemm_tc<0><<<dim3(2, ROWS/128), 256>>>(p_fin, W_out, b_out, p_fo, ROWS, 100, 100);
    // 3. av = [adj_in@fi | adj_out@fo] -> x1[:,0:200]   (TF32x3 mma, per-batch)
    k_av_tc<0>  <<<B_, 128>>>(adj_in,  p_fi);
    k_av_tc<100><<<B_, 128>>>(adj_out, p_fo);
    // 4. gates = sigmoid(x1 @ gate_kernel + gate_bias)
    gemm_tc<1><<<dim3(4, ROWS/128), 256>>>(p_x1, gate_k, gate_b, p_gates, ROWS, 300, 200);
    // 5. x2 = [av | r*h]
    k_x2<<<(ROWS*300 + 255)/256, 256>>>();
    // 6. c = tanh(x2 @ cand_kernel + cand_bias); re = u*h + (1-u)*c
    gemm_tc<2><<<dim3(2, ROWS/128), 256>>>(p_x2, cand_k, cand_b, p_re, ROWS, 300, 100);
    // 7. nasr gathers
    k_nasr<<<B_, 256>>>(alias, mask);
    // 8. seq = seqh @ nasr_w2 ; last = lasth @ nasr_w1
    gemm_tc<0><<<dim3(2, ROWS/128), 256>>>(p_seqh, nasr_w2, nullptr, p_seq, ROWS, 100, 100);
    gemm_tc<0><<<dim3(2, B_/128), 256>>>(p_lasth, nasr_w1, nullptr, p_last, B_, 100, 100);
    // 9. attention -> ma
    k_attn<<<B_, 128>>>(mask, nasr_v, nasr_b);
    // 10. logits = ma @ emb[1:].T   (TF32x3 mma, NT)
    gemm_nt_tc<<<dim3((NLOGITS + 63)/64, B_/128), 256>>>(p_ma, emb + D_, out_logits, B_, (long long)NLOGITS);
    // 11. per-row log-softmax stats + loss
    k_rowstat<<<B_, 256>>>(out_logits, tar);
    k_loss<<<1, 512>>>(out, off);
}

// round 15
// speedup vs baseline: 1.9458x; 1.0001x over previous
#include <cuda_runtime.h>
#include <cstdint>

#define B_ 512
#define N_ 64
#define L_ 64
#define D_ 100
#define NNODES 50000
#define NLOGITS 49999
#define ROWS (B_*N_)   // 32768

// ---------------- scratch (device globals; no allocation allowed) ----------
__device__ float g_fin[ROWS*D_];        // h
__device__ float g_fi [ROWS*D_];
__device__ float g_fo [ROWS*D_];
__device__ float g_x1 [ROWS*3*D_];      // [av(200) | h(100)]
__device__ float g_gates[ROWS*2*D_];    // [r(100) | u(100)]
__device__ float g_x2 [ROWS*3*D_];      // [av(200) | r*h(100)]
__device__ float g_re [ROWS*D_];
__device__ float g_seqh[B_*L_*D_];
__device__ float g_seq [B_*L_*D_];
__device__ float g_lasth[B_*D_];
__device__ float g_last [B_*D_];
__device__ float g_ma   [B_*D_];
__device__ float g_logp [B_];

// ---------------- fast math: FMA-poly exp (avoid MUFU throughput wall) -----
__device__ __forceinline__ float fexp(float x){
    x = fminf(fmaxf(x, -87.0f), 87.0f);
    float n = rintf(x * 1.4426950408889634f);
    float f = fmaf(n, -0.693359375f, x);
    f = fmaf(n, 2.12194440054690583e-4f, f);
    float p = 1.3888889e-3f;
    p = fmaf(p, f, 8.3333333e-3f);
    p = fmaf(p, f, 4.1666667e-2f);
    p = fmaf(p, f, 1.6666667e-1f);
    p = fmaf(p, f, 0.5f);
    p = fmaf(p, f, 1.0f);
    p = fmaf(p, f, 1.0f);
    int e = (int)n;
    float s = __int_as_float((e + 127) << 23);
    return p * s;
}
__device__ __forceinline__ float fsigmoid(float x){
    return __fdividef(1.0f, 1.0f + fexp(-x));
}
__device__ __forceinline__ float ftanh(float x){
    return __fdividef(2.0f, 1.0f + fexp(-2.0f * x)) - 1.0f;
}

// ---------------- TF32 mma helpers ----------------------------------------
__device__ __forceinline__ void mma8(float* d,
                                     uint32_t a0, uint32_t a1, uint32_t a2, uint32_t a3,
                                     uint32_t b0, uint32_t b1){
    asm volatile(
        "mma.sync.aligned.m16n8k8.row.col.f32.tf32.tf32.f32 "
        "{%0,%1,%2,%3}, {%4,%5,%6,%7}, {%8,%9}, {%0,%1,%2,%3};\n"
        : "+f"(d[0]), "+f"(d[1]), "+f"(d[2]), "+f"(d[3])
        : "r"(a0), "r"(a1), "r"(a2), "r"(a3), "r"(b0), "r"(b1));
}
// split fp32 into tf32-exact hi part and exact residual lo (hi = top 19 bits)
__device__ __forceinline__ void split_tf32(float f, uint32_t& hi, uint32_t& lo){
    uint32_t b = __float_as_uint(f);
    hi = b & 0xffffe000u;
    lo = __float_as_uint(f - __uint_as_float(hi));
}

// ---------------- TF32x3 tensor-core GEMM: C = act(A[M,K] @ W[K,N] + b) ----
// BM=128, BN=64, BK=32. 8 warps = 4 (m) x 2 (n); warp tile 32x32.
// sA row stride 36 (==4 mod 32)  -> A-frag LDS conflict-free (bank = 4g+tg)
// sB row stride 72 (==8 mod 32, >=64) -> B-frag LDS conflict-free (bank = 8tg+g)
// MODE 0: optional bias; MODE 1: sigmoid; MODE 2: GRU candidate+update
template<int MODE>
__global__ void __launch_bounds__(256, 2)
gemm_tc(const float* __restrict__ A, const float* __restrict__ W,
        const float* __restrict__ bias, float* __restrict__ C,
        int M, int K, int N)
{
    __shared__ float sA[128*36];
    __shared__ float sB[32*72];
    int m0 = blockIdx.y * 128;
    int n0 = blockIdx.x * 64;
    int tid = threadIdx.x, lane = tid & 31, wid = tid >> 5;
    int wm = wid >> 1, wn = wid & 1;
    int g = lane >> 2, tg = lane & 3;

    float acc[2][4][4] = {};

    int ksteps = (K + 31) / 32;
    for (int kt = 0; kt < ksteps; kt++){
        int k0 = kt * 32;
        // A tile: 128x32 -> 1024 float4
        #pragma unroll
        for (int i = tid; i < 1024; i += 256){
            int r = i >> 3, c4 = (i & 7) * 4;
            float4 v = make_float4(0.f,0.f,0.f,0.f);
            int row = m0 + r, k = k0 + c4;
            if (row < M && k < K)           // K % 4 == 0 at all call sites
                v = *(const float4*)&A[(long long)row * K + k];
            *(float4*)&sA[r*36 + c4] = v;
        }
        // B tile: 32x64 -> 512 float4
        #pragma unroll
        for (int i = tid; i < 512; i += 256){
            int kk = i >> 4, c4 = (i & 15) * 4;
            float4 v = make_float4(0.f,0.f,0.f,0.f);
            int k = k0 + kk, n = n0 + c4;
            if (k < K && n < N)             // N % 4 == 0 at all call sites
                v = *(const float4*)&W[(long long)k * N + n];
            *(float4*)&sB[kk*72 + c4] = v;
        }
        __syncthreads();

        #pragma unroll
        for (int k8 = 0; k8 < 32; k8 += 8){
            uint32_t ah[2][4], al[2][4];
            #pragma unroll
            for (int t = 0; t < 2; t++){
                int rb = wm*32 + t*16;
                float f0 = sA[(rb+g  )*36 + k8+tg  ];
                float f1 = sA[(rb+g+8)*36 + k8+tg  ];
                float f2 = sA[(rb+g  )*36 + k8+tg+4];
                float f3 = sA[(rb+g+8)*36 + k8+tg+4];
                split_tf32(f0, ah[t][0], al[t][0]);
                split_tf32(f1, ah[t][1], al[t][1]);
                split_tf32(f2, ah[t][2], al[t][2]);
                split_tf32(f3, ah[t][3], al[t][3]);
            }
            #pragma unroll
            for (int u = 0; u < 4; u++){
                float b0f = sB[(k8+tg  )*72 + wn*32 + u*8 + g];
                float b1f = sB[(k8+tg+4)*72 + wn*32 + u*8 + g];
                uint32_t bh0, bl0, bh1, bl1;
                split_tf32(b0f, bh0, bl0);
                split_tf32(b1f, bh1, bl1);
                #pragma unroll
                for (int t = 0; t < 2; t++){
                    mma8(acc[t][u], ah[t][0],ah[t][1],ah[t][2],ah[t][3], bl0, bl1);
                    mma8(acc[t][u], al[t][0],al[t][1],al[t][2],al[t][3], bh0, bh1);
                    mma8(acc[t][u], ah[t][0],ah[t][1],ah[t][2],ah[t][3], bh0, bh1);
                }
            }
        }
        __syncthreads();
    }

    #pragma unroll
    for (int t = 0; t < 2; t++){
        #pragma unroll
        for (int u = 0; u < 4; u++){
            #pragma unroll
            for (int i = 0; i < 4; i++){
                int row = m0 + wm*32 + t*16 + g + ((i >= 2) ? 8 : 0);
                int col = n0 + wn*32 + u*8 + tg*2 + (i & 1);
                if (row >= M || col >= N) continue;
                float v = acc[t][u][i];
                if (bias) v += bias[col];
                if (MODE == 1) v = fsigmoid(v);
                if (MODE == 2){
                    float c = ftanh(v);
                    float uu = g_gates[row*200 + 100 + col];
                    float h  = g_fin[row*100 + col];
                    v = uu*h + (1.0f - uu)*c;
                }
                C[(long long)row * N + col] = v;
            }
        }
    }
}

// ---------------- logits (NT): C[m,n] = dot(A[m,:], E[n,:]), TF32x3 -------
__global__ void __launch_bounds__(256, 2)
gemm_nt_tc(const float* __restrict__ A, const float* __restrict__ E,
           float* __restrict__ C, int M, long long NC)
{
    __shared__ float sA[128*36];
    __shared__ float sE[64*36];
    int m0 = blockIdx.y * 128;
    long long n0 = (long long)blockIdx.x * 64;
    int tid = threadIdx.x, lane = tid & 31, wid = tid >> 5;
    int wm = wid >> 1, wn = wid & 1;
    int g = lane >> 2, tg = lane & 3;

    float acc[2][4][4] = {};

    for (int kt = 0; kt < 4; kt++){       // K = 100 padded to 128
        int k0 = kt * 32;
        #pragma unroll
        for (int i = tid; i < 1024; i += 256){
            int r = i >> 3, c4 = (i & 7) * 4;
            float4 v = make_float4(0.f,0.f,0.f,0.f);
            int row = m0 + r, k = k0 + c4;
            if (row < M && k < 100)
                v = *(const float4*)&A[(long long)row * 100 + k];
            *(float4*)&sA[r*36 + c4] = v;
        }
        #pragma unroll
        for (int i = tid; i < 512; i += 256){
            int r = i >> 3, c4 = (i & 7) * 4;
            float4 v = make_float4(0.f,0.f,0.f,0.f);
            long long n = n0 + r;
            int k = k0 + c4;
            if (n < NC && k < 100)
                v = *(const float4*)&E[n * 100 + k];
            *(float4*)&sE[r*36 + c4] = v;
        }
        __syncthreads();

        #pragma unroll
        for (int k8 = 0; k8 < 32; k8 += 8){
            uint32_t ah[2][4], al[2][4];
            #pragma unroll
            for (int t = 0; t < 2; t++){
                int rb = wm*32 + t*16;
                float f0 = sA[(rb+g  )*36 + k8+tg  ];
                float f1 = sA[(rb+g+8)*36 + k8+tg  ];
                float f2 = sA[(rb+g  )*36 + k8+tg+4];
                float f3 = sA[(rb+g+8)*36 + k8+tg+4];
                split_tf32(f0, ah[t][0], al[t][0]);
                split_tf32(f1, ah[t][1], al[t][1]);
                split_tf32(f2, ah[t][2], al[t][2]);
                split_tf32(f3, ah[t][3], al[t][3]);
            }
            #pragma unroll
            for (int u = 0; u < 4; u++){
                int nl = wn*32 + u*8 + g;
                float b0f = sE[nl*36 + k8+tg  ];
                float b1f = sE[nl*36 + k8+tg+4];
                uint32_t bh0, bl0, bh1, bl1;
                split_tf32(b0f, bh0, bl0);
                split_tf32(b1f, bh1, bl1);
                #pragma unroll
                for (int t = 0; t < 2; t++){
                    mma8(acc[t][u], ah[t][0],ah[t][1],ah[t][2],ah[t][3], bl0, bl1);
                    mma8(acc[t][u], al[t][0],al[t][1],al[t][2],al[t][3], bh0, bh1);
                    mma8(acc[t][u], ah[t][0],ah[t][1],ah[t][2],ah[t][3], bh0, bh1);
                }
            }
        }
        __syncthreads();
    }

    #pragma unroll
    for (int t = 0; t < 2; t++){
        #pragma unroll
        for (int u = 0; u < 4; u++){
            #pragma unroll
            for (int i = 0; i < 4; i++){
                int row = m0 + wm*32 + t*16 + g + ((i >= 2) ? 8 : 0);
                long long col = n0 + wn*32 + u*8 + tg*2 + (i & 1);
                if (row >= M || col >= NC) continue;
                C[(long long)row * NC + col] = acc[t][u][i];
            }
        }
    }
}

// ---------------- av via mma: x1[:, OFF..OFF+100) = adj[b] @ F[b] ----------
// per block: one batch. A = adj (64x64), B = F tile (64 k x 100 n, k-major).
// 4 warps, each owns 16 rows x 104 cols (13 n-tiles).
// sAdj stride 68 (==4 mod 32); sF stride 104 (==8 mod 32): conflict-free frags.
template<int OFF>
__global__ void __launch_bounds__(128)
k_av_tc(const float* __restrict__ adj, const float* __restrict__ F)
{
    __shared__ float sAdj[64*68];
    __shared__ float sF[64*104];
    int b = blockIdx.x;
    int tid = threadIdx.x, lane = tid & 31, wid = tid >> 5;
    int g = lane >> 2, tg = lane & 3;

    #pragma unroll
    for (int i = tid; i < 1024; i += 128){          // adj: 64x64
        int r = i >> 4, c4 = (i & 15) * 4;
        *(float4*)&sAdj[r*68 + c4] = *(const float4*)&adj[b*4096 + r*64 + c4];
    }
    #pragma unroll
    for (int i = tid; i < 1600; i += 128){          // F: 64x100
        int r = i / 25, c4 = (i % 25) * 4;
        *(float4*)&sF[r*104 + c4] = *(const float4*)&F[(b*64 + r)*100 + c4];
    }
    for (int r = tid; r < 64; r += 128){            // zero pad cols 100..103
        sF[r*104+100] = 0.f; sF[r*104+101] = 0.f;
        sF[r*104+102] = 0.f; sF[r*104+103] = 0.f;
    }
    __syncthreads();

    float acc[13][4] = {};
    int rb = wid * 16;
    #pragma unroll
    for (int k8 = 0; k8 < 64; k8 += 8){
        float f0 = sAdj[(rb+g  )*68 + k8+tg  ];
        float f1 = sAdj[(rb+g+8)*68 + k8+tg  ];
        float f2 = sAdj[(rb+g  )*68 + k8+tg+4];
        float f3 = sAdj[(rb+g+8)*68 + k8+tg+4];
        uint32_t ah0,al0,ah1,al1,ah2,al2,ah3,al3;
        split_tf32(f0, ah0, al0); split_tf32(f1, ah1, al1);
        split_tf32(f2, ah2, al2); split_tf32(f3, ah3, al3);
        #pragma unroll
        for (int u = 0; u < 13; u++){
            float b0f = sF[(k8+tg  )*104 + u*8 + g];
            float b1f = sF[(k8+tg+4)*104 + u*8 + g];
            uint32_t bh0, bl0, bh1, bl1;
            split_tf32(b0f, bh0, bl0);
            split_tf32(b1f, bh1, bl1);
            mma8(acc[u], ah0,ah1,ah2,ah3, bl0, bl1);
            mma8(acc[u], al0,al1,al2,al3, bh0, bh1);
            mma8(acc[u], ah0,ah1,ah2,ah3, bh0, bh1);
        }
    }

    float* x1 = g_x1 + b*64*300;
    #pragma unroll
    for (int u = 0; u < 13; u++){
        #pragma unroll
        for (int i = 0; i < 4; i++){
            int row = rb + g + ((i >= 2) ? 8 : 0);
            int col = u*8 + tg*2 + (i & 1);
            if (col < 100)
                x1[row*300 + OFF + col] = acc[u][i];
        }
    }
}

// ---------------- small kernels --------------------------------------------
__global__ void k_gather(const float* __restrict__ emb, const int* __restrict__ item){
    int t = blockIdx.x * 256 + threadIdx.x;
    if (t >= ROWS * D_) return;
    int idx = t / D_, d = t % D_;
    float v = emb[(long long)item[idx] * D_ + d];
    g_fin[t] = v;
    g_x1[idx * 300 + 200 + d] = v;   // h-part of concat for gates GEMM
}

// x2 = [av | r*h]
__global__ void k_x2(){
    int t = blockIdx.x * 256 + threadIdx.x;
    if (t >= ROWS * 300) return;
    int row = t / 300, c = t % 300;
    float v;
    if (c < 200) v = g_x1[t];
    else {
        int d = c - 200;
        v = g_gates[row*200 + d] * g_fin[row*100 + d];
    }
    g_x2[t] = v;
}

// per-batch: rm, last_id, gather seq_h and last_h
__global__ void k_nasr(const int* __restrict__ alias, const float* __restrict__ mask){
    int b = blockIdx.x;
    __shared__ int s_alias[64];
    __shared__ int s_last;
    if (threadIdx.x < 64) s_alias[threadIdx.x] = alias[b*64 + threadIdx.x];
    __syncthreads();
    if (threadIdx.x == 0){
        float s = 0.0f;
        for (int l = 0; l < 64; l++) s += mask[b*64 + l];
        int rm = (int)(s + 0.5f);
        if (rm < 1) rm = 1;
        s_last = s_alias[rm - 1];
    }
    __syncthreads();
    for (int t = threadIdx.x; t < 64*100; t += 256){
        int l = t / 100, d = t % 100;
        g_seqh[(b*64 + l)*100 + d] = g_re[(b*64 + s_alias[l])*100 + d];
    }
    for (int d = threadIdx.x; d < 100; d += 256)
        g_lasth[b*100 + d] = g_re[(b*64 + s_last)*100 + d];
}

// attention: coef + weighted sum -> ma
__global__ void k_attn(const float* __restrict__ mask, const float* __restrict__ nasr_v,
                       const float* __restrict__ nasr_b){
    int b = blockIdx.x;
    int tid = threadIdx.x;               // 128 threads
    __shared__ float s_last[100], s_v[100], s_nb[100], s_coef[64];
    if (tid < 100){
        s_last[tid] = g_last[b*100 + tid];
        s_v[tid]    = nasr_v[tid];
        s_nb[tid]   = nasr_b[tid];
    }
    __syncthreads();
    int w = tid >> 5, lane = tid & 31;
    for (int l = w; l < 64; l += 4){
        float part = 0.0f;
        for (int d = lane; d < 100; d += 32){
            float x = s_last[d] + g_seq[(b*64 + l)*100 + d] + s_nb[d];
            part = fmaf(fsigmoid(x), s_v[d], part);
        }
        #pragma unroll
        for (int o = 16; o > 0; o >>= 1) part += __shfl_down_sync(0xffffffffu, part, o);
        if (lane == 0) s_coef[l] = part * mask[b*64 + l];
    }
    __syncthreads();
    for (int d = tid; d < 100; d += 128){
        float acc = 0.0f;
        for (int l = 0; l < 64; l++)
            acc = fmaf(s_coef[l], g_seqh[(b*64 + l)*100 + d], acc);
        g_ma[b*100 + d] = acc;
    }
}

// per-row online max/sumexp over logits, then logp[label]
__global__ void k_rowstat(const float* __restrict__ logits, const int* __restrict__ tar){
    int b = blockIdx.x;
    const float* row = logits + (long long)b * NLOGITS;
    int tid = threadIdx.x;
    float m = -1e30f, s = 0.0f;
    for (int j = tid; j < NLOGITS; j += 256){
        float x = row[j];
        if (x > m){ s = fmaf(s, fexp(m - x), 1.0f); m = x; }
        else       s += fexp(x - m);
    }
    __shared__ float sm[256], ss[256];
    sm[tid] = m; ss[tid] = s;
    __syncthreads();
    for (int o = 128; o > 0; o >>= 1){
        if (tid < o){
            float m2 = sm[tid+o], s2 = ss[tid+o];
            float M = fmaxf(sm[tid], m2);
            ss[tid] = ss[tid]*fexp(sm[tid]-M) + s2*fexp(m2-M);
            sm[tid] = M;
        }
        __syncthreads();
    }
    if (tid == 0){
        int lab = tar[b] - 1;
        g_logp[b] = row[lab] - sm[0] - logf(ss[0]);
    }
}

__global__ void k_loss(float* __restrict__ out, int off){
    __shared__ float sh[512];
    int tid = threadIdx.x;
    sh[tid] = g_logp[tid];
    __syncthreads();
    for (int o = 256; o > 0; o >>= 1){
        if (tid < o) sh[tid] += sh[tid+o];
        __syncthreads();
    }
    if (tid == 0){
        float loss = -sh[0] / (float)B_;
        for (int i = 0; i < off; i++) out[i] = loss;
    }
}

// ---------------- host ------------------------------------------------------
static float* symf(const void* s){ void* p = nullptr; cudaGetSymbolAddress(&p, s); return (float*)p; }

extern "C" void kernel_launch(void* const* d_in, const int* in_sizes, int n_in,
                              void* d_out, int out_size)
{
    const float* adj_in   = (const float*)d_in[0];
    const float* adj_out  = (const float*)d_in[1];
    const int*   item     = (const int*)  d_in[2];
    const int*   alias    = (const int*)  d_in[3];
    const float* mask     = (const float*)d_in[4];
    const int*   tar      = (const int*)  d_in[5];
    const float* emb      = (const float*)d_in[6];
    const float* W_in     = (const float*)d_in[7];
    const float* b_in     = (const float*)d_in[8];
    const float* W_out    = (const float*)d_in[9];
    const float* b_out    = (const float*)d_in[10];
    const float* gate_k   = (const float*)d_in[11];
    const float* gate_b   = (const float*)d_in[12];
    const float* cand_k   = (const float*)d_in[13];
    const float* cand_b   = (const float*)d_in[14];
    const float* nasr_w1  = (const float*)d_in[15];
    const float* nasr_w2  = (const float*)d_in[16];
    const float* nasr_v   = (const float*)d_in[17];
    const float* nasr_b   = (const float*)d_in[18];

    float* out = (float*)d_out;
    long long nlog = (long long)B_ * NLOGITS;
    int off = out_size - (int)nlog;
    if (off < 0) off = 0;
    float* out_logits = out + off;

    float* p_fin   = symf(g_fin);
    float* p_fi    = symf(g_fi);
    float* p_fo    = symf(g_fo);
    float* p_x1    = symf(g_x1);
    float* p_gates = symf(g_gates);
    float* p_x2    = symf(g_x2);
    float* p_re    = symf(g_re);
    float* p_seqh  = symf(g_seqh);
    float* p_seq   = symf(g_seq);
    float* p_lasth = symf(g_lasth);
    float* p_last  = symf(g_last);
    float* p_ma    = symf(g_ma);

    // 1. gather embeddings (also fills h-part of x1)
    k_gather<<<(ROWS*D_ + 255)/256, 256>>>(emb, item);
    // 2. fi = fin@W_in + b_in ; fo = fin@W_out + b_out   (TF32x3 mma)
    gemm_tc<0><<<dim3(2, ROWS/128), 256>>>(p_fin, W_in,  b_in,  p_fi, ROWS, 100, 100);
    gemm_tc<0><<<dim3(2, ROWS/128), 256>>>(p_fin, W_out, b_out, p_fo, ROWS, 100, 100);
    // 3. av = [adj_in@fi | adj_out@fo] -> x1[:,0:200]   (TF32x3 mma, per-batch)
    k_av_tc<0>  <<<B_, 128>>>(adj_in,  p_fi);
    k_av_tc<100><<<B_, 128>>>(adj_out, p_fo);
    // 4. gates = sigmoid(x1 @ gate_kernel + gate_bias)
    gemm_tc<1><<<dim3(4, ROWS/128), 256>>>(p_x1, gate_k, gate_b, p_gates, ROWS, 300, 200);
    // 5. x2 = [av | r*h]
    k_x2<<<(ROWS*300 + 255)/256, 256>>>();
    // 6. c = tanh(x2 @ cand_kernel + cand_bias); re = u*h + (1-u)*c
    gemm_tc<2><<<dim3(2, ROWS/128), 256>>>(p_x2, cand_k, cand_b, p_re, ROWS, 300, 100);
    // 7. nasr gathers
    k_nasr<<<B_, 256>>>(alias, mask);
    // 8. seq = seqh @ nasr_w2 ; last = lasth @ nasr_w1
    gemm_tc<0><<<dim3(2, ROWS/128), 256>>>(p_seqh, nasr_w2, nullptr, p_seq, ROWS, 100, 100);
    gemm_tc<0><<<dim3(2, B_/128), 256>>>(p_lasth, nasr_w1, nullptr, p_last, B_, 100, 100);
    // 9. attention -> ma
    k_attn<<<B_, 128>>>(mask, nasr_v, nasr_b);
    // 10. logits = ma @ emb[1:].T   (TF32x3 mma, NT)
    gemm_nt_tc<<<dim3((NLOGITS + 63)/64, B_/128), 256>>>(p_ma, emb + D_, out_logits, B_, (long long)NLOGITS);
    // 11. per-row log-softmax stats + loss
    k_rowstat<<<B_, 256>>>(out_logits, tar);
    k_loss<<<1, 512>>>(out, off);
}

// round 16
// speedup vs baseline: 2.1945x; 1.1278x over previous
#include <cuda_runtime.h>
#include <cstdint>

#define B_ 512
#define N_ 64
#define L_ 64
#define D_ 100
#define NNODES 50000
#define NLOGITS 49999
#define ROWS (B_*N_)   // 32768

// ---------------- scratch (device globals; no allocation allowed) ----------
__device__ float g_fin[ROWS*D_];        // h
__device__ float g_fi [ROWS*D_];
__device__ float g_fo [ROWS*D_];
__device__ float g_x1 [ROWS*3*D_];      // [av(200) | h(100)]
__device__ float g_gates[ROWS*2*D_];    // [r(100) | u(100)]
__device__ float g_x2 [ROWS*3*D_];      // [av(200) | r*h(100)]
__device__ float g_re [ROWS*D_];
__device__ float g_seqh[B_*L_*D_];
__device__ float g_seq [B_*L_*D_];
__device__ float g_lasth[B_*D_];
__device__ float g_last [B_*D_];
__device__ float g_ma   [B_*D_];
__device__ float g_logp [B_];

// ---------------- fast math: FMA-poly exp (avoid MUFU throughput wall) -----
__device__ __forceinline__ float fexp(float x){
    x = fminf(fmaxf(x, -87.0f), 87.0f);
    float n = rintf(x * 1.4426950408889634f);
    float f = fmaf(n, -0.693359375f, x);
    f = fmaf(n, 2.12194440054690583e-4f, f);
    float p = 1.3888889e-3f;
    p = fmaf(p, f, 8.3333333e-3f);
    p = fmaf(p, f, 4.1666667e-2f);
    p = fmaf(p, f, 1.6666667e-1f);
    p = fmaf(p, f, 0.5f);
    p = fmaf(p, f, 1.0f);
    p = fmaf(p, f, 1.0f);
    int e = (int)n;
    float s = __int_as_float((e + 127) << 23);
    return p * s;
}
__device__ __forceinline__ float fsigmoid(float x){
    return __fdividef(1.0f, 1.0f + fexp(-x));
}
__device__ __forceinline__ float ftanh(float x){
    return __fdividef(2.0f, 1.0f + fexp(-2.0f * x)) - 1.0f;
}

// ---------------- mma wrappers ---------------------------------------------
__device__ __forceinline__ void mma16(float* d,
                                      uint32_t a0, uint32_t a1, uint32_t a2, uint32_t a3,
                                      uint32_t b0, uint32_t b1){
    asm volatile(
        "mma.sync.aligned.m16n8k16.row.col.f32.bf16.bf16.f32 "
        "{%0,%1,%2,%3}, {%4,%5,%6,%7}, {%8,%9}, {%0,%1,%2,%3};\n"
        : "+f"(d[0]), "+f"(d[1]), "+f"(d[2]), "+f"(d[3])
        : "r"(a0), "r"(a1), "r"(a2), "r"(a3), "r"(b0), "r"(b1));
}
__device__ __forceinline__ void mma8(float* d,
                                     uint32_t a0, uint32_t a1, uint32_t a2, uint32_t a3,
                                     uint32_t b0, uint32_t b1){
    asm volatile(
        "mma.sync.aligned.m16n8k8.row.col.f32.tf32.tf32.f32 "
        "{%0,%1,%2,%3}, {%4,%5,%6,%7}, {%8,%9}, {%0,%1,%2,%3};\n"
        : "+f"(d[0]), "+f"(d[1]), "+f"(d[2]), "+f"(d[3])
        : "r"(a0), "r"(a1), "r"(a2), "r"(a3), "r"(b0), "r"(b1));
}
// split fp32 into tf32-exact hi part and exact residual lo (hi = top 19 bits)
__device__ __forceinline__ void split_tf32(float f, uint32_t& hi, uint32_t& lo){
    uint32_t b = __float_as_uint(f);
    hi = b & 0xffffe000u;
    lo = __float_as_uint(f - __uint_as_float(hi));
}
// split a (even,odd) fp32 pair into packed bf16 hi-pair and residual lo-pair.
// low 16 bits of each packed word = even (lower-k) element.
__device__ __forceinline__ void bsplit2(float fe, float fo, uint32_t& hp, uint32_t& lp){
    uint32_t h;
    asm("cvt.rn.bf16x2.f32 %0, %1, %2;" : "=r"(h) : "f"(fo), "f"(fe));
    float he = __uint_as_float(h << 16);
    float ho = __uint_as_float(h & 0xffff0000u);
    float le = fe - he;
    float lo = fo - ho;
    uint32_t l;
    asm("cvt.rn.bf16x2.f32 %0, %1, %2;" : "=r"(l) : "f"(lo), "f"(le));
    hp = h; lp = l;
}

// ---------------- BF16x3 tensor-core GEMM: C = act(A[M,K] @ W[K,N] + b) ----
// BM=128, BN=64, BK=32 (16 k-pairs). 8 warps = 4(m) x 2(n); warp tile 32x32.
// A pair arrays: row stride 20 words (==4 mod 32) -> A-frag bank = 4g+tg, unique
// B pair arrays: pair-row stride 72 words (==8 mod 32) -> B-frag bank = 8tg+g, unique
// MODE 0: optional bias; MODE 1: sigmoid; MODE 2: GRU candidate+update
template<int MODE>
__global__ void __launch_bounds__(256, 2)
gemm_tc(const float* __restrict__ A, const float* __restrict__ W,
        const float* __restrict__ bias, float* __restrict__ C,
        int M, int K, int N)
{
    __shared__ uint32_t sAh[128*20], sAl[128*20];   // 16 pairs + 4 pad
    __shared__ uint32_t sBh[16*72],  sBl[16*72];    // 16 pair-rows, 64 n + 8 pad
    int m0 = blockIdx.y * 128;
    int n0 = blockIdx.x * 64;
    int tid = threadIdx.x, lane = tid & 31, wid = tid >> 5;
    int wm = wid >> 1, wn = wid & 1;
    int g = lane >> 2, tg = lane & 3;

    float acc[2][4][4] = {};

    int ksteps = (K + 31) / 32;
    for (int kt = 0; kt < ksteps; kt++){
        int k0 = kt * 32;
        // A tile: 128x32 floats = 1024 float4, 4 per thread
        #pragma unroll
        for (int i = tid; i < 1024; i += 256){
            int r = i >> 3, c4 = (i & 7) * 4;
            float4 v = make_float4(0.f,0.f,0.f,0.f);
            int row = m0 + r, k = k0 + c4;
            if (row < M && k < K)            // K % 4 == 0 at all call sites
                v = *(const float4*)&A[(long long)row * K + k];
            uint32_t h0,l0,h1,l1;
            bsplit2(v.x, v.y, h0, l0);
            bsplit2(v.z, v.w, h1, l1);
            int p = c4 >> 1;
            sAh[r*20 + p] = h0; sAh[r*20 + p + 1] = h1;
            sAl[r*20 + p] = l0; sAl[r*20 + p + 1] = l1;
        }
        // B tile: 32x64 floats; 256 threads each handle one (pair-row, 4-col) chunk
        {
            int p  = tid >> 4;              // 0..15 pair row
            int c4 = (tid & 15) * 4;        // 0..60
            int ka = k0 + 2*p, kb = ka + 1;
            int n  = n0 + c4;
            float4 va = make_float4(0.f,0.f,0.f,0.f);
            float4 vb = make_float4(0.f,0.f,0.f,0.f);
            if (ka < K && n < N) va = *(const float4*)&W[(long long)ka * N + n];
            if (kb < K && n < N) vb = *(const float4*)&W[(long long)kb * N + n];
            uint32_t h, l;
            bsplit2(va.x, vb.x, h, l); sBh[p*72 + c4+0] = h; sBl[p*72 + c4+0] = l;
            bsplit2(va.y, vb.y, h, l); sBh[p*72 + c4+1] = h; sBl[p*72 + c4+1] = l;
            bsplit2(va.z, vb.z, h, l); sBh[p*72 + c4+2] = h; sBl[p*72 + c4+2] = l;
            bsplit2(va.w, vb.w, h, l); sBh[p*72 + c4+3] = h; sBl[p*72 + c4+3] = l;
        }
        __syncthreads();

        #pragma unroll
        for (int kk = 0; kk < 2; kk++){
            int pb = kk * 8;
            uint32_t ah[2][4], al[2][4];
            #pragma unroll
            for (int t = 0; t < 2; t++){
                int rb = wm*32 + t*16;
                ah[t][0] = sAh[(rb+g  )*20 + pb+tg  ];
                ah[t][1] = sAh[(rb+g+8)*20 + pb+tg  ];
                ah[t][2] = sAh[(rb+g  )*20 + pb+tg+4];
                ah[t][3] = sAh[(rb+g+8)*20 + pb+tg+4];
                al[t][0] = sAl[(rb+g  )*20 + pb+tg  ];
                al[t][1] = sAl[(rb+g+8)*20 + pb+tg  ];
                al[t][2] = sAl[(rb+g  )*20 + pb+tg+4];
                al[t][3] = sAl[(rb+g+8)*20 + pb+tg+4];
            }
            #pragma unroll
            for (int u = 0; u < 4; u++){
                int col = wn*32 + u*8 + g;
                uint32_t bh0 = sBh[(pb+tg  )*72 + col];
                uint32_t bh1 = sBh[(pb+tg+4)*72 + col];
                uint32_t bl0 = sBl[(pb+tg  )*72 + col];
                uint32_t bl1 = sBl[(pb+tg+4)*72 + col];
                #pragma unroll
                for (int t = 0; t < 2; t++){
                    mma16(acc[t][u], ah[t][0],ah[t][1],ah[t][2],ah[t][3], bl0, bl1);
                    mma16(acc[t][u], al[t][0],al[t][1],al[t][2],al[t][3], bh0, bh1);
                    mma16(acc[t][u], ah[t][0],ah[t][1],ah[t][2],ah[t][3], bh0, bh1);
                }
            }
        }
        __syncthreads();
    }

    #pragma unroll
    for (int t = 0; t < 2; t++){
        #pragma unroll
        for (int u = 0; u < 4; u++){
            #pragma unroll
            for (int i = 0; i < 4; i++){
                int row = m0 + wm*32 + t*16 + g + ((i >= 2) ? 8 : 0);
                int col = n0 + wn*32 + u*8 + tg*2 + (i & 1);
                if (row >= M || col >= N) continue;
                float v = acc[t][u][i];
                if (bias) v += bias[col];
                if (MODE == 1) v = fsigmoid(v);
                if (MODE == 2){
                    float c = ftanh(v);
                    float uu = g_gates[row*200 + 100 + col];
                    float h  = g_fin[row*100 + col];
                    v = uu*h + (1.0f - uu)*c;
                }
                C[(long long)row * N + col] = v;
            }
        }
    }
}

// ---------------- logits (NT): C[m,n] = dot(A[m,:], E[n,:]), BF16x3 --------
__global__ void __launch_bounds__(256, 2)
gemm_nt_tc(const float* __restrict__ A, const float* __restrict__ E,
           float* __restrict__ C, int M, long long NC)
{
    __shared__ uint32_t sAh[128*20], sAl[128*20];
    __shared__ uint32_t sEh[64*20],  sEl[64*20];
    int m0 = blockIdx.y * 128;
    long long n0 = (long long)blockIdx.x * 64;
    int tid = threadIdx.x, lane = tid & 31, wid = tid >> 5;
    int wm = wid >> 1, wn = wid & 1;
    int g = lane >> 2, tg = lane & 3;

    float acc[2][4][4] = {};

    for (int kt = 0; kt < 4; kt++){       // K = 100 padded to 128
        int k0 = kt * 32;
        #pragma unroll
        for (int i = tid; i < 1024; i += 256){
            int r = i >> 3, c4 = (i & 7) * 4;
            float4 v = make_float4(0.f,0.f,0.f,0.f);
            int row = m0 + r, k = k0 + c4;
            if (row < M && k < 100)
                v = *(const float4*)&A[(long long)row * 100 + k];
            uint32_t h0,l0,h1,l1;
            bsplit2(v.x, v.y, h0, l0);
            bsplit2(v.z, v.w, h1, l1);
            int p = c4 >> 1;
            sAh[r*20 + p] = h0; sAh[r*20 + p + 1] = h1;
            sAl[r*20 + p] = l0; sAl[r*20 + p + 1] = l1;
        }
        #pragma unroll
        for (int i = tid; i < 512; i += 256){   // E: 64 rows x 32 k
            int r = i >> 3, c4 = (i & 7) * 4;
            float4 v = make_float4(0.f,0.f,0.f,0.f);
            long long n = n0 + r;
            int k = k0 + c4;
            if (n < NC && k < 100)
                v = *(const float4*)&E[n * 100 + k];
            uint32_t h0,l0,h1,l1;
            bsplit2(v.x, v.y, h0, l0);   // pairs along k within the float4
            bsplit2(v.z, v.w, h1, l1);
            int p = c4 >> 1;
            sEh[r*20 + p] = h0; sEh[r*20 + p + 1] = h1;
            sEl[r*20 + p] = l0; sEl[r*20 + p + 1] = l1;
        }
        __syncthreads();

        #pragma unroll
        for (int kk = 0; kk < 2; kk++){
            int pb = kk * 8;
            uint32_t ah[2][4], al[2][4];
            #pragma unroll
            for (int t = 0; t < 2; t++){
                int rb = wm*32 + t*16;
                ah[t][0] = sAh[(rb+g  )*20 + pb+tg  ];
                ah[t][1] = sAh[(rb+g+8)*20 + pb+tg  ];
                ah[t][2] = sAh[(rb+g  )*20 + pb+tg+4];
                ah[t][3] = sAh[(rb+g+8)*20 + pb+tg+4];
                al[t][0] = sAl[(rb+g  )*20 + pb+tg  ];
                al[t][1] = sAl[(rb+g+8)*20 + pb+tg  ];
                al[t][2] = sAl[(rb+g  )*20 + pb+tg+4];
                al[t][3] = sAl[(rb+g+8)*20 + pb+tg+4];
            }
            #pragma unroll
            for (int u = 0; u < 4; u++){
                int nl = wn*32 + u*8 + g;
                uint32_t bh0 = sEh[nl*20 + pb+tg  ];
                uint32_t bh1 = sEh[nl*20 + pb+tg+4];
                uint32_t bl0 = sEl[nl*20 + pb+tg  ];
                uint32_t bl1 = sEl[nl*20 + pb+tg+4];
                #pragma unroll
                for (int t = 0; t < 2; t++){
                    mma16(acc[t][u], ah[t][0],ah[t][1],ah[t][2],ah[t][3], bl0, bl1);
                    mma16(acc[t][u], al[t][0],al[t][1],al[t][2],al[t][3], bh0, bh1);
                    mma16(acc[t][u], ah[t][0],ah[t][1],ah[t][2],ah[t][3], bh0, bh1);
                }
            }
        }
        __syncthreads();
    }

    #pragma unroll
    for (int t = 0; t < 2; t++){
        #pragma unroll
        for (int u = 0; u < 4; u++){
            #pragma unroll
            for (int i = 0; i < 4; i++){
                int row = m0 + wm*32 + t*16 + g + ((i >= 2) ? 8 : 0);
                long long col = n0 + wn*32 + u*8 + tg*2 + (i & 1);
                if (row >= M || col >= NC) continue;
                C[(long long)row * NC + col] = acc[t][u][i];
            }
        }
    }
}

// ---------------- av via mma (TF32x3): x1[:, OFF..OFF+100) = adj[b] @ F[b] -
template<int OFF>
__global__ void __launch_bounds__(128)
k_av_tc(const float* __restrict__ adj, const float* __restrict__ F)
{
    __shared__ float sAdj[64*68];
    __shared__ float sF[64*104];
    int b = blockIdx.x;
    int tid = threadIdx.x, lane = tid & 31, wid = tid >> 5;
    int g = lane >> 2, tg = lane & 3;

    #pragma unroll
    for (int i = tid; i < 1024; i += 128){          // adj: 64x64
        int r = i >> 4, c4 = (i & 15) * 4;
        *(float4*)&sAdj[r*68 + c4] = *(const float4*)&adj[b*4096 + r*64 + c4];
    }
    #pragma unroll
    for (int i = tid; i < 1600; i += 128){          // F: 64x100
        int r = i / 25, c4 = (i % 25) * 4;
        *(float4*)&sF[r*104 + c4] = *(const float4*)&F[(b*64 + r)*100 + c4];
    }
    for (int r = tid; r < 64; r += 128){            // zero pad cols 100..103
        sF[r*104+100] = 0.f; sF[r*104+101] = 0.f;
        sF[r*104+102] = 0.f; sF[r*104+103] = 0.f;
    }
    __syncthreads();

    float acc[13][4] = {};
    int rb = wid * 16;
    #pragma unroll
    for (int k8 = 0; k8 < 64; k8 += 8){
        float f0 = sAdj[(rb+g  )*68 + k8+tg  ];
        float f1 = sAdj[(rb+g+8)*68 + k8+tg  ];
        float f2 = sAdj[(rb+g  )*68 + k8+tg+4];
        float f3 = sAdj[(rb+g+8)*68 + k8+tg+4];
        uint32_t ah0,al0,ah1,al1,ah2,al2,ah3,al3;
        split_tf32(f0, ah0, al0); split_tf32(f1, ah1, al1);
        split_tf32(f2, ah2, al2); split_tf32(f3, ah3, al3);
        #pragma unroll
        for (int u = 0; u < 13; u++){
            float b0f = sF[(k8+tg  )*104 + u*8 + g];
            float b1f = sF[(k8+tg+4)*104 + u*8 + g];
            uint32_t bh0, bl0, bh1, bl1;
            split_tf32(b0f, bh0, bl0);
            split_tf32(b1f, bh1, bl1);
            mma8(acc[u], ah0,ah1,ah2,ah3, bl0, bl1);
            mma8(acc[u], al0,al1,al2,al3, bh0, bh1);
            mma8(acc[u], ah0,ah1,ah2,ah3, bh0, bh1);
        }
    }

    float* x1 = g_x1 + b*64*300;
    #pragma unroll
    for (int u = 0; u < 13; u++){
        #pragma unroll
        for (int i = 0; i < 4; i++){
            int row = rb + g + ((i >= 2) ? 8 : 0);
            int col = u*8 + tg*2 + (i & 1);
            if (col < 100)
                x1[row*300 + OFF + col] = acc[u][i];
        }
    }
}

// ---------------- small kernels --------------------------------------------
__global__ void k_gather(const float* __restrict__ emb, const int* __restrict__ item){
    int t = blockIdx.x * 256 + threadIdx.x;
    if (t >= ROWS * D_) return;
    int idx = t / D_, d = t % D_;
    float v = emb[(long long)item[idx] * D_ + d];
    g_fin[t] = v;
    g_x1[idx * 300 + 200 + d] = v;   // h-part of concat for gates GEMM
}

// x2 = [av | r*h]
__global__ void k_x2(){
    int t = blockIdx.x * 256 + threadIdx.x;
    if (t >= ROWS * 300) return;
    int row = t / 300, c = t % 300;
    float v;
    if (c < 200) v = g_x1[t];
    else {
        int d = c - 200;
        v = g_gates[row*200 + d] * g_fin[row*100 + d];
    }
    g_x2[t] = v;
}

// per-batch: rm, last_id, gather seq_h and last_h
__global__ void k_nasr(const int* __restrict__ alias, const float* __restrict__ mask){
    int b = blockIdx.x;
    __shared__ int s_alias[64];
    __shared__ int s_last;
    if (threadIdx.x < 64) s_alias[threadIdx.x] = alias[b*64 + threadIdx.x];
    __syncthreads();
    if (threadIdx.x == 0){
        float s = 0.0f;
        for (int l = 0; l < 64; l++) s += mask[b*64 + l];
        int rm = (int)(s + 0.5f);
        if (rm < 1) rm = 1;
        s_last = s_alias[rm - 1];
    }
    __syncthreads();
    for (int t = threadIdx.x; t < 64*100; t += 256){
        int l = t / 100, d = t % 100;
        g_seqh[(b*64 + l)*100 + d] = g_re[(b*64 + s_alias[l])*100 + d];
    }
    for (int d = threadIdx.x; d < 100; d += 256)
        g_lasth[b*100 + d] = g_re[(b*64 + s_last)*100 + d];
}

// attention: coef + weighted sum -> ma
__global__ void k_attn(const float* __restrict__ mask, const float* __restrict__ nasr_v,
                       const float* __restrict__ nasr_b){
    int b = blockIdx.x;
    int tid = threadIdx.x;               // 128 threads
    __shared__ float s_last[100], s_v[100], s_nb[100], s_coef[64];
    if (tid < 100){
        s_last[tid] = g_last[b*100 + tid];
        s_v[tid]    = nasr_v[tid];
        s_nb[tid]   = nasr_b[tid];
    }
    __syncthreads();
    int w = tid >> 5, lane = tid & 31;
    for (int l = w; l < 64; l += 4){
        float part = 0.0f;
        for (int d = lane; d < 100; d += 32){
            float x = s_last[d] + g_seq[(b*64 + l)*100 + d] + s_nb[d];
            part = fmaf(fsigmoid(x), s_v[d], part);
        }
        #pragma unroll
        for (int o = 16; o > 0; o >>= 1) part += __shfl_down_sync(0xffffffffu, part, o);
        if (lane == 0) s_coef[l] = part * mask[b*64 + l];
    }
    __syncthreads();
    for (int d = tid; d < 100; d += 128){
        float acc = 0.0f;
        for (int l = 0; l < 64; l++)
            acc = fmaf(s_coef[l], g_seqh[(b*64 + l)*100 + d], acc);
        g_ma[b*100 + d] = acc;
    }
}

// per-row online max/sumexp over logits, then logp[label]
__global__ void k_rowstat(const float* __restrict__ logits, const int* __restrict__ tar){
    int b = blockIdx.x;
    const float* row = logits + (long long)b * NLOGITS;
    int tid = threadIdx.x;
    float m = -1e30f, s = 0.0f;
    for (int j = tid; j < NLOGITS; j += 256){
        float x = row[j];
        if (x > m){ s = fmaf(s, fexp(m - x), 1.0f); m = x; }
        else       s += fexp(x - m);
    }
    __shared__ float sm[256], ss[256];
    sm[tid] = m; ss[tid] = s;
    __syncthreads();
    for (int o = 128; o > 0; o >>= 1){
        if (tid < o){
            float m2 = sm[tid+o], s2 = ss[tid+o];
            float M = fmaxf(sm[tid], m2);
            ss[tid] = ss[tid]*fexp(sm[tid]-M) + s2*fexp(m2-M);
            sm[tid] = M;
        }
        __syncthreads();
    }
    if (tid == 0){
        int lab = tar[b] - 1;
        g_logp[b] = row[lab] - sm[0] - logf(ss[0]);
    }
}

__global__ void k_loss(float* __restrict__ out, int off){
    __shared__ float sh[512];
    int tid = threadIdx.x;
    sh[tid] = g_logp[tid];
    __syncthreads();
    for (int o = 256; o > 0; o >>= 1){
        if (tid < o) sh[tid] += sh[tid+o];
        __syncthreads();
    }
    if (tid == 0){
        float loss = -sh[0] / (float)B_;
        for (int i = 0; i < off; i++) out[i] = loss;
    }
}

// ---------------- host ------------------------------------------------------
static float* symf(const void* s){ void* p = nullptr; cudaGetSymbolAddress(&p, s); return (float*)p; }

extern "C" void kernel_launch(void* const* d_in, const int* in_sizes, int n_in,
                              void* d_out, int out_size)
{
    const float* adj_in   = (const float*)d_in[0];
    const float* adj_out  = (const float*)d_in[1];
    const int*   item     = (const int*)  d_in[2];
    const int*   alias    = (const int*)  d_in[3];
    const float* mask     = (const float*)d_in[4];
    const int*   tar      = (const int*)  d_in[5];
    const float* emb      = (const float*)d_in[6];
    const float* W_in     = (const float*)d_in[7];
    const float* b_in     = (const float*)d_in[8];
    const float* W_out    = (const float*)d_in[9];
    const float* b_out    = (const float*)d_in[10];
    const float* gate_k   = (const float*)d_in[11];
    const float* gate_b   = (const float*)d_in[12];
    const float* cand_k   = (const float*)d_in[13];
    const float* cand_b   = (const float*)d_in[14];
    const float* nasr_w1  = (const float*)d_in[15];
    const float* nasr_w2  = (const float*)d_in[16];
    const float* nasr_v   = (const float*)d_in[17];
    const float* nasr_b   = (const float*)d_in[18];

    float* out = (float*)d_out;
    long long nlog = (long long)B_ * NLOGITS;
    int off = out_size - (int)nlog;
    if (off < 0) off = 0;
    float* out_logits = out + off;

    float* p_fin   = symf(g_fin);
    float* p_fi    = symf(g_fi);
    float* p_fo    = symf(g_fo);
    float* p_x1    = symf(g_x1);
    float* p_gates = symf(g_gates);
    float* p_x2    = symf(g_x2);
    float* p_re    = symf(g_re);
    float* p_seqh  = symf(g_seqh);
    float* p_seq   = symf(g_seq);
    float* p_lasth = symf(g_lasth);
    float* p_last  = symf(g_last);
    float* p_ma    = symf(g_ma);

    // 1. gather embeddings (also fills h-part of x1)
    k_gather<<<(ROWS*D_ + 255)/256, 256>>>(emb, item);
    // 2. fi = fin@W_in + b_in ; fo = fin@W_out + b_out   (BF16x3 mma)
    gemm_tc<0><<<dim3(2, ROWS/128), 256>>>(p_fin, W_in,  b_in,  p_fi, ROWS, 100, 100);
    gemm_tc<0><<<dim3(2, ROWS/128), 256>>>(p_fin, W_out, b_out, p_fo, ROWS, 100, 100);
    // 3. av = [adj_in@fi | adj_out@fo] -> x1[:,0:200]   (TF32x3 mma, per-batch)
    k_av_tc<0>  <<<B_, 128>>>(adj_in,  p_fi);
    k_av_tc<100><<<B_, 128>>>(adj_out, p_fo);
    // 4. gates = sigmoid(x1 @ gate_kernel + gate_bias)
    gemm_tc<1><<<dim3(4, ROWS/128), 256>>>(p_x1, gate_k, gate_b, p_gates, ROWS, 300, 200);
    // 5. x2 = [av | r*h]
    k_x2<<<(ROWS*300 + 255)/256, 256>>>();
    // 6. c = tanh(x2 @ cand_kernel + cand_bias); re = u*h + (1-u)*c
    gemm_tc<2><<<dim3(2, ROWS/128), 256>>>(p_x2, cand_k, cand_b, p_re, ROWS, 300, 100);
    // 7. nasr gathers
    k_nasr<<<B_, 256>>>(alias, mask);
    // 8. seq = seqh @ nasr_w2 ; last = lasth @ nasr_w1
    gemm_tc<0><<<dim3(2, ROWS/128), 256>>>(p_seqh, nasr_w2, nullptr, p_seq, ROWS, 100, 100);
    gemm_tc<0><<<dim3(2, B_/128), 256>>>(p_lasth, nasr_w1, nullptr, p_last, B_, 100, 100);
    // 9. attention -> ma
    k_attn<<<B_, 128>>>(mask, nasr_v, nasr_b);
    // 10. logits = ma @ emb[1:].T   (BF16x3 mma, NT)
    gemm_nt_tc<<<dim3((NLOGITS + 63)/64, B_/128), 256>>>(p_ma, emb + D_, out_logits, B_, (long long)NLOGITS);
    // 11. per-row log-softmax stats + loss
    k_rowstat<<<B_, 256>>>(out_logits, tar);
    k_loss<<<1, 512>>>(out, off);
}